// round 15
// baseline (speedup 1.0000x reference)
#include <cuda_runtime.h>
#include <cuda_bf16.h>

// out[i,j,:] = W[:,p] + W[:,66+t] + e*W[:,132] + W[:,133+s]
//
// Fused table (138 rows x 128 ch, channel-contiguous), as in R4/R7:
//   T[r]     = W[:,r]  + W[:,131]     (r in 0..65)   covers (p, t=131)
//   T[66+dt] = W[:,32] + W[:,66+dt]   (dt in 0..65)  covers (p=32, t) [ri==rj]
//   T[132+k] = W[:,133+k] + (k<5 ? W[:,132] : 0)     entity-folded chain rows
// Hot loop: o = T[pt] + T[ch] -> 2 LDS.128 + 1 STG.128, branch-free, in-order.
//
// R12 = R7 body UNCHANGED (table copy first, indices second — their latencies
// overlap) + PDL with the grid-sync as the very first statement, so only the
// launch ramp overlaps the prepass. No intra-kernel reordering (R11's mistake).

#define N_TBL_ROWS 138
#define CZ 128
#define NO_BINS 139
#define THREADS 512
#define NWARPS (THREADS / 32)

__device__ float g_tbl[N_TBL_ROWS * CZ];

__global__ void build_tbl_kernel(const float* __restrict__ W) {
    int idx = blockIdx.x * blockDim.x + threadIdx.x;
    if (idx < N_TBL_ROWS * CZ) {
        int row = idx >> 7;        // 0..137
        int c   = idx & (CZ - 1);  // 0..127
        const float* Wc = W + c * NO_BINS;
        float v;
        if (row < 66) {
            v = Wc[row] + Wc[131];            // (p, t=131) fused
        } else if (row < 132) {
            v = Wc[32] + Wc[row];             // (p=32, t) fused (ri==rj case)
        } else {
            int k = row - 132;                // 0..5
            v = Wc[133 + k];
            if (k < 5) v += Wc[132];          // entity flag folded in
        }
        g_tbl[idx] = v;
    }
    cudaTriggerProgrammaticLaunchCompletion();
}

__global__ __launch_bounds__(THREADS, 3) void relpos_kernel(
    const int* __restrict__ asym,
    const int* __restrict__ res,
    const int* __restrict__ ent,
    const int* __restrict__ tok,
    const int* __restrict__ sym,
    float* __restrict__ out,
    int N)
{
    // Wait for prepass writes FIRST — everything below is identical to R7,
    // so the intra-kernel copy/compute overlap is preserved.
    cudaGridDependencySynchronize();

    extern __shared__ float smem[];
    float*    s_tbl = smem;                                   // 138*128 floats
    unsigned* s_idx = (unsigned*)(smem + N_TBL_ROWS * CZ);    // N packed indices

    const int tid = threadIdx.x;
    const int i   = blockIdx.x;

    // --- Prologue A: table -> SMEM (coalesced float4, conflict-free) ---
    {
        float4*       dst = (float4*)s_tbl;
        const float4* src = (const float4*)g_tbl;
        #pragma unroll
        for (int k = tid; k < (N_TBL_ROWS * CZ) / 4; k += THREADS) dst[k] = src[k];
    }

    // --- Prologue B: per-j fused indices (pt, ch) packed into one u32 ---
    const int ai = __ldg(asym + i);
    const int ri = __ldg(res  + i);
    const int ei = __ldg(ent  + i);
    const int ti = __ldg(tok  + i);
    const int si = __ldg(sym  + i);

    for (int j = tid; j < N; j += THREADS) {
        int aj = __ldg(asym + j);
        int rj = __ldg(res  + j);
        int ej = __ldg(ent  + j);
        int tj = __ldg(tok  + j);
        int sj = __ldg(sym  + j);

        bool sc = (ai == aj);
        bool sr = (ri == rj);

        int p  = min(max(ri - rj + 32, 0), 64);   // 0..64
        int dt = min(max(ti - tj + 32, 0), 64);   // 0..64
        int pt = sc ? (sr ? (66 + dt) : p) : 65;

        int ds = min(max(si - sj + 2, 0), 4);
        int ch = (ei == ej) ? (132 + ds) : 137;

        s_idx[j] = (unsigned)pt | ((unsigned)ch << 8);
    }
    __syncthreads();

    // --- Hot loop: warp-per-pair, in-order, branch-free: 2 LDS.128 + STG.128 ---
    const int warp = tid >> 5;
    const int lane = tid & 31;
    const float4* tbl4 = (const float4*)s_tbl;
    float* orow = out + (size_t)i * N * CZ + lane * 4;

    #pragma unroll 4
    for (int j = warp; j < N; j += NWARPS) {
        unsigned pk = s_idx[j];
        int pt = pk & 0xFFu;
        int ch = pk >> 8;

        float4 a = tbl4[pt * 32 + lane];
        float4 c = tbl4[ch * 32 + lane];

        float4 o;
        o.x = a.x + c.x;
        o.y = a.y + c.y;
        o.z = a.z + c.z;
        o.w = a.w + c.w;

        __stcs((float4*)(orow + (size_t)j * CZ), o);
    }
}

extern "C" void kernel_launch(void* const* d_in, const int* in_sizes, int n_in,
                              void* d_out, int out_size) {
    const int*   asym = (const int*)d_in[0];
    const int*   res  = (const int*)d_in[1];
    const int*   ent  = (const int*)d_in[2];
    const int*   tok  = (const int*)d_in[3];
    const int*   sym  = (const int*)d_in[4];
    const float* W    = (const float*)d_in[5];
    float*       out  = (float*)d_out;

    const int N = in_sizes[0];  // 1024

    build_tbl_kernel<<<(N_TBL_ROWS * CZ + 255) / 256, 256>>>(W);

    const int smem_bytes = N_TBL_ROWS * CZ * (int)sizeof(float) + N * (int)sizeof(unsigned);
    cudaFuncSetAttribute(relpos_kernel, cudaFuncAttributeMaxDynamicSharedMemorySize, smem_bytes);

    cudaLaunchAttribute attrs[1];
    attrs[0].id = cudaLaunchAttributeProgrammaticStreamSerialization;
    attrs[0].val.programmaticStreamSerializationAllowed = 1;

    cudaLaunchConfig_t cfg = {};
    cfg.gridDim = dim3(N, 1, 1);
    cfg.blockDim = dim3(THREADS, 1, 1);
    cfg.dynamicSmemBytes = (size_t)smem_bytes;
    cfg.stream = 0;
    cfg.attrs = attrs;
    cfg.numAttrs = 1;

    cudaLaunchKernelEx(&cfg, relpos_kernel, asym, res, ent, tok, sym, out, N);
}

// round 16
// speedup vs baseline: 1.0055x; 1.0055x over previous
#include <cuda_runtime.h>
#include <cuda_bf16.h>

// out[i,j,:] = W[:,p] + W[:,66+t] + e*W[:,132] + W[:,133+s]
//
// Fused table (138 rows x 128 ch, channel-contiguous), as in R4/R7:
//   T[r]     = W[:,r]  + W[:,131]     (r in 0..65)   covers (p, t=131)
//   T[66+dt] = W[:,32] + W[:,66+dt]   (dt in 0..65)  covers (p=32, t) [ri==rj]
//   T[132+k] = W[:,133+k] + (k<5 ? W[:,132] : 0)     entity-folded chain rows
// Hot loop: o = T[pt] + T[ch] -> 2 LDS.128 + 1 STG.128, branch-free, in-order.
//
// R13 = R7 main kernel UNCHANGED + COALESCED prepass: index mapping flipped to
// c = idx/138, row = idx%138 so consecutive lanes read consecutive W addresses
// (scattered g_tbl stores are fire-and-forget; strided loads were the cost).

#define N_TBL_ROWS 138
#define CZ 128
#define NO_BINS 139
#define THREADS 512
#define NWARPS (THREADS / 32)

__device__ float g_tbl[N_TBL_ROWS * CZ];

__global__ void build_tbl_kernel(const float* __restrict__ W) {
    int idx = blockIdx.x * blockDim.x + threadIdx.x;
    if (idx >= N_TBL_ROWS * CZ) return;
    int c   = idx / N_TBL_ROWS;        // 0..127  (warp-uniform-ish)
    int row = idx - c * N_TBL_ROWS;    // 0..137  (consecutive across lanes)
    const float* Wc = W + c * NO_BINS;
    float v;
    if (row < 66) {
        v = Wc[row] + Wc[131];            // coalesced + same-line broadcast
    } else if (row < 132) {
        v = Wc[32] + Wc[row];             // coalesced + broadcast
    } else {
        int k = row - 132;                // 0..5
        v = Wc[133 + k];
        if (k < 5) v += Wc[132];
    }
    g_tbl[row * CZ + c] = v;              // scattered STG.32 (fire-and-forget)
}

__global__ __launch_bounds__(THREADS, 3) void relpos_kernel(
    const int* __restrict__ asym,
    const int* __restrict__ res,
    const int* __restrict__ ent,
    const int* __restrict__ tok,
    const int* __restrict__ sym,
    float* __restrict__ out,
    int N)
{
    extern __shared__ float smem[];
    float*    s_tbl = smem;                                   // 138*128 floats
    unsigned* s_idx = (unsigned*)(smem + N_TBL_ROWS * CZ);    // N packed indices

    const int tid = threadIdx.x;
    const int i   = blockIdx.x;

    // --- Prologue A: table -> SMEM (coalesced float4, conflict-free) ---
    {
        float4*       dst = (float4*)s_tbl;
        const float4* src = (const float4*)g_tbl;
        #pragma unroll
        for (int k = tid; k < (N_TBL_ROWS * CZ) / 4; k += THREADS) dst[k] = src[k];
    }

    // --- Prologue B: per-j fused indices (pt, ch) packed into one u32 ---
    const int ai = __ldg(asym + i);
    const int ri = __ldg(res  + i);
    const int ei = __ldg(ent  + i);
    const int ti = __ldg(tok  + i);
    const int si = __ldg(sym  + i);

    for (int j = tid; j < N; j += THREADS) {
        int aj = __ldg(asym + j);
        int rj = __ldg(res  + j);
        int ej = __ldg(ent  + j);
        int tj = __ldg(tok  + j);
        int sj = __ldg(sym  + j);

        bool sc = (ai == aj);
        bool sr = (ri == rj);

        int p  = min(max(ri - rj + 32, 0), 64);   // 0..64
        int dt = min(max(ti - tj + 32, 0), 64);   // 0..64
        int pt = sc ? (sr ? (66 + dt) : p) : 65;

        int ds = min(max(si - sj + 2, 0), 4);
        int ch = (ei == ej) ? (132 + ds) : 137;

        s_idx[j] = (unsigned)pt | ((unsigned)ch << 8);
    }
    __syncthreads();

    // --- Hot loop: warp-per-pair, in-order, branch-free: 2 LDS.128 + STG.128 ---
    const int warp = tid >> 5;
    const int lane = tid & 31;
    const float4* tbl4 = (const float4*)s_tbl;
    float* orow = out + (size_t)i * N * CZ + lane * 4;

    #pragma unroll 4
    for (int j = warp; j < N; j += NWARPS) {
        unsigned pk = s_idx[j];
        int pt = pk & 0xFFu;
        int ch = pk >> 8;

        float4 a = tbl4[pt * 32 + lane];
        float4 c = tbl4[ch * 32 + lane];

        float4 o;
        o.x = a.x + c.x;
        o.y = a.y + c.y;
        o.z = a.z + c.z;
        o.w = a.w + c.w;

        __stcs((float4*)(orow + (size_t)j * CZ), o);
    }
}

extern "C" void kernel_launch(void* const* d_in, const int* in_sizes, int n_in,
                              void* d_out, int out_size) {
    const int*   asym = (const int*)d_in[0];
    const int*   res  = (const int*)d_in[1];
    const int*   ent  = (const int*)d_in[2];
    const int*   tok  = (const int*)d_in[3];
    const int*   sym  = (const int*)d_in[4];
    const float* W    = (const float*)d_in[5];
    float*       out  = (float*)d_out;

    const int N = in_sizes[0];  // 1024

    build_tbl_kernel<<<(N_TBL_ROWS * CZ + 255) / 256, 256>>>(W);

    const int smem_bytes = N_TBL_ROWS * CZ * (int)sizeof(float) + N * (int)sizeof(unsigned);
    cudaFuncSetAttribute(relpos_kernel, cudaFuncAttributeMaxDynamicSharedMemorySize, smem_bytes);
    relpos_kernel<<<N, THREADS, smem_bytes>>>(asym, res, ent, tok, sym, out, N);
}

// round 17
// speedup vs baseline: 1.0728x; 1.0670x over previous
#include <cuda_runtime.h>
#include <cuda_bf16.h>

// out[i,j,:] = W[:,p] + W[:,66+t] + e*W[:,132] + W[:,133+s]
//
// Fused table (138 rows x 128 ch, channel-contiguous):
//   T[r]     = W[:,r]  + W[:,131]     (r in 0..65)   covers (p, t=131)
//   T[66+dt] = W[:,32] + W[:,66+dt]   (dt in 0..65)  covers (p=32, t) [ri==rj]
//   T[132+k] = W[:,133+k] + (k<5 ? W[:,132] : 0)     entity-folded chain rows
// Hot loop: o = T[pt] + T[ch] -> 2 LDS.128 + 1 STG.128, branch-free, in-order,
// warp-per-pair. 512 threads, 3 CTAs/SM. This is the measured champion (R7).

#define N_TBL_ROWS 138
#define CZ 128
#define NO_BINS 139
#define THREADS 512
#define NWARPS (THREADS / 32)

__device__ float g_tbl[N_TBL_ROWS * CZ];

__global__ void build_tbl_kernel(const float* __restrict__ W) {
    int idx = blockIdx.x * blockDim.x + threadIdx.x;
    if (idx >= N_TBL_ROWS * CZ) return;
    int row = idx >> 7;        // 0..137
    int c   = idx & (CZ - 1);  // 0..127
    const float* Wc = W + c * NO_BINS;
    float v;
    if (row < 66) {
        v = Wc[row] + Wc[131];            // (p, t=131) fused
    } else if (row < 132) {
        v = Wc[32] + Wc[row];             // (p=32, t) fused (ri==rj case)
    } else {
        int k = row - 132;                // 0..5
        v = Wc[133 + k];
        if (k < 5) v += Wc[132];          // entity flag folded in
    }
    g_tbl[idx] = v;
}

__global__ __launch_bounds__(THREADS, 3) void relpos_kernel(
    const int* __restrict__ asym,
    const int* __restrict__ res,
    const int* __restrict__ ent,
    const int* __restrict__ tok,
    const int* __restrict__ sym,
    float* __restrict__ out,
    int N)
{
    extern __shared__ float smem[];
    float*    s_tbl = smem;                                   // 138*128 floats
    unsigned* s_idx = (unsigned*)(smem + N_TBL_ROWS * CZ);    // N packed indices

    const int tid = threadIdx.x;
    const int i   = blockIdx.x;

    // --- Prologue A: table -> SMEM (coalesced float4, conflict-free) ---
    {
        float4*       dst = (float4*)s_tbl;
        const float4* src = (const float4*)g_tbl;
        #pragma unroll
        for (int k = tid; k < (N_TBL_ROWS * CZ) / 4; k += THREADS) dst[k] = src[k];
    }

    // --- Prologue B: per-j fused indices (pt, ch) packed into one u32 ---
    const int ai = __ldg(asym + i);
    const int ri = __ldg(res  + i);
    const int ei = __ldg(ent  + i);
    const int ti = __ldg(tok  + i);
    const int si = __ldg(sym  + i);

    for (int j = tid; j < N; j += THREADS) {
        int aj = __ldg(asym + j);
        int rj = __ldg(res  + j);
        int ej = __ldg(ent  + j);
        int tj = __ldg(tok  + j);
        int sj = __ldg(sym  + j);

        bool sc = (ai == aj);
        bool sr = (ri == rj);

        int p  = min(max(ri - rj + 32, 0), 64);   // 0..64
        int dt = min(max(ti - tj + 32, 0), 64);   // 0..64
        int pt = sc ? (sr ? (66 + dt) : p) : 65;

        int ds = min(max(si - sj + 2, 0), 4);
        int ch = (ei == ej) ? (132 + ds) : 137;

        s_idx[j] = (unsigned)pt | ((unsigned)ch << 8);
    }
    __syncthreads();

    // --- Hot loop: warp-per-pair, in-order, branch-free: 2 LDS.128 + STG.128 ---
    const int warp = tid >> 5;
    const int lane = tid & 31;
    const float4* tbl4 = (const float4*)s_tbl;
    float* orow = out + (size_t)i * N * CZ + lane * 4;

    #pragma unroll 4
    for (int j = warp; j < N; j += NWARPS) {
        unsigned pk = s_idx[j];
        int pt = pk & 0xFFu;
        int ch = pk >> 8;

        float4 a = tbl4[pt * 32 + lane];
        float4 c = tbl4[ch * 32 + lane];

        float4 o;
        o.x = a.x + c.x;
        o.y = a.y + c.y;
        o.z = a.z + c.z;
        o.w = a.w + c.w;

        __stcs((float4*)(orow + (size_t)j * CZ), o);
    }
}

extern "C" void kernel_launch(void* const* d_in, const int* in_sizes, int n_in,
                              void* d_out, int out_size) {
    const int*   asym = (const int*)d_in[0];
    const int*   res  = (const int*)d_in[1];
    const int*   ent  = (const int*)d_in[2];
    const int*   tok  = (const int*)d_in[3];
    const int*   sym  = (const int*)d_in[4];
    const float* W    = (const float*)d_in[5];
    float*       out  = (float*)d_out;

    const int N = in_sizes[0];  // 1024

    build_tbl_kernel<<<(N_TBL_ROWS * CZ + 255) / 256, 256>>>(W);

    const int smem_bytes = N_TBL_ROWS * CZ * (int)sizeof(float) + N * (int)sizeof(unsigned);
    cudaFuncSetAttribute(relpos_kernel, cudaFuncAttributeMaxDynamicSharedMemorySize, smem_bytes);
    relpos_kernel<<<N, THREADS, smem_bytes>>>(asym, res, ent, tok, sym, out, N);
}